// round 9
// baseline (speedup 1.0000x reference)
#include <cuda_runtime.h>
#include <math.h>
#include <stdint.h>

#define H    1024
#define V    32000
#define B    32
#define T    64
#define G3H  3072
#define BM   256               // logits m-tile
#define NMT  (V / BM)          // 125 logits m-tiles (single wave on 148 SMs)
#define KSP  4                 // GRU K-split
#define GPITCH 162             // gru As pitch (stride-10 groups, 16 tm lanes)
#define LPITCH 322             // logits As pitch: 322 mod 32 == 2
#define BPITCH 36
#define LKT  16                // logits k-tile (double buffered)
#define OUT_LOGP 65536000LL    // B*T*V

typedef unsigned long long ull;

// ---------------- device scratch (no allocations allowed) ----------------
__device__ float g_h[2][H * B];           // hidden, transposed [k][b], double buffer
__device__ float g_Cb[KSP][B][2 * G3H];   // GRU gate partials [ksplit][b][m]
__device__ float g_pval[B][NMT];          // per-m-tile argmax partials
__device__ int   g_pidx[B][NMT];
__device__ float g_rowmax[B * T];         // max logit per (b,t) for log_softmax
__device__ int   g_tok[B];

// ---------------- packed fp32x2 helpers ----------------
__device__ __forceinline__ ull splat2(float x) {
    ull r; asm("mov.b64 %0, {%1, %1};" : "=l"(r) : "f"(x)); return r;
}
__device__ __forceinline__ void fma2(ull& d, ull a, ull b) {
    asm("fma.rn.f32x2 %0, %1, %2, %0;" : "+l"(d) : "l"(a), "l"(b));
}
__device__ __forceinline__ float2 unpk(ull v) {
    float2 f; asm("mov.b64 {%0, %1}, %2;" : "=f"(f.x), "=f"(f.y) : "l"(v)); return f;
}

// map m-row r to stride-10 group column
__device__ __forceinline__ int acol(int r) { return (r >> 3) * 10 + (r & 7); }

// =====================================================================
// init: h0 = encoder_hidden[0] transposed; tok = SOS(0)
// =====================================================================
__global__ void init_k(const float* __restrict__ enc_h)
{
    int b = blockIdx.x, k = threadIdx.x;          // 32 x 1024
    g_h[0][k * B + b] = enc_h[b * H + k];
    if (b == 0 && k < B) g_tok[k] = 0;
}

// =====================================================================
// GRU gates GEMM, K-split (structure unchanged from R8).
// =====================================================================
__global__ void __launch_bounds__(128) gru_gemm(
    const float* __restrict__ Wih, const float* __restrict__ Whh,
    const float* __restrict__ emb, int t)
{
    const int m0 = blockIdx.x * 128;
    const int ks = blockIdx.y;
    const bool ih = (m0 < G3H);
    const float* __restrict__ Wm = ih ? (Wih + (size_t)m0 * H)
                                      : (Whh + (size_t)(m0 - G3H) * H);
    const float* __restrict__ hb = g_h[t & 1];

    __shared__ float As[32][GPITCH];
    __shared__ float Bs[32][BPITCH];
    __shared__ int   srow[B];

    const int tid = threadIdx.x;
    const int tm = tid & 15;
    const int tb = tid >> 4;
    const int lr = tid >> 2;
    const int lc = tid & 3;
    const int bk = tid >> 2;
    const int bb = (tid & 3) * 8;

    if (ih) {
        if (t > 0) {
            int b = tid >> 2, li = tid & 3;
            float v = -INFINITY; int idx = 0x7fffffff;
            for (int i = li; i < NMT; i += 4) {
                float pv = g_pval[b][i]; int pi = g_pidx[b][i];
                if (pv > v || (pv == v && pi < idx)) { v = pv; idx = pi; }
            }
            #pragma unroll
            for (int off = 2; off > 0; off >>= 1) {
                float ov = __shfl_down_sync(0xffffffffu, v, off, 4);
                int   oi = __shfl_down_sync(0xffffffffu, idx, off, 4);
                if (ov > v || (ov == v && oi < idx)) { v = ov; idx = oi; }
            }
            if (li == 0) {
                srow[b] = idx * H;
                if (blockIdx.x == 0 && ks == 0) g_rowmax[b * T + (t - 1)] = v;
            }
        } else if (tid < B) {
            srow[tid] = 0;
        }
        __syncthreads();
    }

    const int kbase = ks * (H / KSP);

    float4 apre[8];
    float4 bq0, bq1;
    {
        const int k0 = kbase;
        #pragma unroll
        for (int p = 0; p < 4; p++) {
            const float* wr = Wm + (size_t)(p * 32 + lr) * H + k0;
            apre[p * 2 + 0] = *(const float4*)(wr + 4 * lc);
            apre[p * 2 + 1] = *(const float4*)(wr + 16 + 4 * lc);
        }
        if (ih) {
            int kg = k0 + bk;
            bq0.x = fmaxf(emb[(size_t)srow[bb + 0] + kg], 0.f);
            bq0.y = fmaxf(emb[(size_t)srow[bb + 1] + kg], 0.f);
            bq0.z = fmaxf(emb[(size_t)srow[bb + 2] + kg], 0.f);
            bq0.w = fmaxf(emb[(size_t)srow[bb + 3] + kg], 0.f);
            bq1.x = fmaxf(emb[(size_t)srow[bb + 4] + kg], 0.f);
            bq1.y = fmaxf(emb[(size_t)srow[bb + 5] + kg], 0.f);
            bq1.z = fmaxf(emb[(size_t)srow[bb + 6] + kg], 0.f);
            bq1.w = fmaxf(emb[(size_t)srow[bb + 7] + kg], 0.f);
        } else {
            bq0 = *(const float4*)(hb + (k0 + bk) * B + bb);
            bq1 = *(const float4*)(hb + (k0 + bk) * B + bb + 4);
        }
    }

    ull acc[4][4];
    #pragma unroll
    for (int p = 0; p < 4; p++)
        #pragma unroll
        for (int j = 0; j < 4; j++) acc[p][j] = 0ull;

    for (int kt = 0; kt < 8; kt++) {
        #pragma unroll
        for (int p = 0; p < 4; p++) {
            int col = acol(p * 32 + lr);
            float4 v0 = apre[p * 2 + 0];
            float4 v1 = apre[p * 2 + 1];
            int ka = 4 * lc, kb2 = 16 + 4 * lc;
            As[ka + 0][col] = v0.x; As[ka + 1][col] = v0.y;
            As[ka + 2][col] = v0.z; As[ka + 3][col] = v0.w;
            As[kb2 + 0][col] = v1.x; As[kb2 + 1][col] = v1.y;
            As[kb2 + 2][col] = v1.z; As[kb2 + 3][col] = v1.w;
        }
        *(float4*)&Bs[bk][bb]     = bq0;
        *(float4*)&Bs[bk][bb + 4] = bq1;
        __syncthreads();

        if (kt + 1 < 8) {
            const int k0 = kbase + (kt + 1) * 32;
            #pragma unroll
            for (int p = 0; p < 4; p++) {
                const float* wr = Wm + (size_t)(p * 32 + lr) * H + k0;
                apre[p * 2 + 0] = *(const float4*)(wr + 4 * lc);
                apre[p * 2 + 1] = *(const float4*)(wr + 16 + 4 * lc);
            }
            if (ih) {
                int kg = k0 + bk;
                bq0.x = fmaxf(emb[(size_t)srow[bb + 0] + kg], 0.f);
                bq0.y = fmaxf(emb[(size_t)srow[bb + 1] + kg], 0.f);
                bq0.z = fmaxf(emb[(size_t)srow[bb + 2] + kg], 0.f);
                bq0.w = fmaxf(emb[(size_t)srow[bb + 3] + kg], 0.f);
                bq1.x = fmaxf(emb[(size_t)srow[bb + 4] + kg], 0.f);
                bq1.y = fmaxf(emb[(size_t)srow[bb + 5] + kg], 0.f);
                bq1.z = fmaxf(emb[(size_t)srow[bb + 6] + kg], 0.f);
                bq1.w = fmaxf(emb[(size_t)srow[bb + 7] + kg], 0.f);
            } else {
                bq0 = *(const float4*)(hb + (k0 + bk) * B + bb);
                bq1 = *(const float4*)(hb + (k0 + bk) * B + bb + 4);
            }
        }

        #pragma unroll 16
        for (int kk = 0; kk < 32; kk++) {
            const float* ab = &As[kk][10 * tm];
            ull a0 = *(const ull*)(ab + 0);
            ull a1 = *(const ull*)(ab + 2);
            ull a2 = *(const ull*)(ab + 4);
            ull a3 = *(const ull*)(ab + 6);
            float4 bv = *(const float4*)&Bs[kk][4 * tb];
            ull s;
            s = splat2(bv.x); fma2(acc[0][0], a0, s); fma2(acc[1][0], a1, s); fma2(acc[2][0], a2, s); fma2(acc[3][0], a3, s);
            s = splat2(bv.y); fma2(acc[0][1], a0, s); fma2(acc[1][1], a1, s); fma2(acc[2][1], a2, s); fma2(acc[3][1], a3, s);
            s = splat2(bv.z); fma2(acc[0][2], a0, s); fma2(acc[1][2], a1, s); fma2(acc[2][2], a2, s); fma2(acc[3][2], a3, s);
            s = splat2(bv.w); fma2(acc[0][3], a0, s); fma2(acc[1][3], a1, s); fma2(acc[2][3], a2, s); fma2(acc[3][3], a3, s);
        }
        __syncthreads();
    }

    #pragma unroll
    for (int j = 0; j < 4; j++) {
        int b = 4 * tb + j;
        float2 p0 = unpk(acc[0][j]), p1 = unpk(acc[1][j]);
        float2 p2 = unpk(acc[2][j]), p3 = unpk(acc[3][j]);
        float4 o0 = make_float4(p0.x, p0.y, p1.x, p1.y);
        float4 o1 = make_float4(p2.x, p2.y, p3.x, p3.y);
        *(float4*)&g_Cb[ks][b][m0 + 8 * tm]     = o0;
        *(float4*)&g_Cb[ks][b][m0 + 8 * tm + 4] = o1;
    }
}

// =====================================================================
// GRU cell: sum K-split partials + biases -> h_new (buffer (t+1)&1)
// =====================================================================
__global__ void __launch_bounds__(256) gru_cell(
    const float* __restrict__ bih, const float* __restrict__ bhh, int t)
{
    int gid = blockIdx.x * 256 + threadIdx.x;      // 32768
    int b = gid >> 10;
    int j = gid & 1023;
    float gir = 0.f, giz = 0.f, gin = 0.f, ghr = 0.f, ghz = 0.f, ghn = 0.f;
    #pragma unroll
    for (int s = 0; s < KSP; s++) {
        const float* C = g_Cb[s][b];
        gir += C[j];           giz += C[H + j];       gin += C[2 * H + j];
        ghr += C[G3H + j];     ghz += C[G3H + H + j]; ghn += C[G3H + 2 * H + j];
    }
    float r = 1.f / (1.f + expf(-(gir + bih[j]       + ghr + bhh[j])));
    float z = 1.f / (1.f + expf(-(giz + bih[H + j]   + ghz + bhh[H + j])));
    float n = tanhf(gin + bih[2 * H + j] + r * (ghn + bhh[2 * H + j]));
    float hold = g_h[t & 1][j * B + b];
    g_h[(t + 1) & 1][j * B + b] = (1.f - z) * n + z * hold;
}

// =====================================================================
// Logits GEMM: BM=256, grid=125 (one wave), 256 threads (2 warps/SMSP).
// 8 warps = 2 m-halves x 4 b-octets; lane: tm=lane&15 (A broadcast),
// bq=lane>>4. Per-thread 8m x 4b. Double-buffered smem, k-tile 16,
// one __syncthreads per tile.
// =====================================================================
__global__ void __launch_bounds__(256) logits_gemm(
    const float* __restrict__ Wout, const float* __restrict__ bout,
    float* __restrict__ out, int t)
{
    const int mt = blockIdx.x;
    const int m0 = mt * BM;
    const float* __restrict__ Wm = Wout + (size_t)m0 * H;
    const float* __restrict__ hb = g_h[(t + 1) & 1];

    __shared__ float As[2][LKT][LPITCH];  // [buf][kk][col], col=(m>>3)*10+(m&7)
    __shared__ float Bs[2][LKT][BPITCH];
    __shared__ float sv[B][2];            // per-b per-mhalf argmax partials
    __shared__ int   si[B][2];

    const int tid  = threadIdx.x;
    const int lane = tid & 31;
    const int w    = tid >> 5;
    const int mh   = w >> 2;              // m half: 0 -> m 0..127, 1 -> 128..255
    const int bbase = (w & 3) * 8;        // warp's 8-b octet
    const int tm   = lane & 15;
    const int bq   = lane >> 4;           // b quad within octet
    // A loader: one row per thread
    const int lcol = acol(tid);           // column for m = tid
    // B loader
    const int bk  = tid >> 4;             // k 0..15
    const int bb2 = (tid & 15) * 2;       // b pair

    float4 ap[4];
    float2 bp;
    {
        const float* wr = Wm + (size_t)tid * H;
        #pragma unroll
        for (int q = 0; q < 4; q++) ap[q] = *(const float4*)(wr + 4 * q);
        bp = *(const float2*)(hb + bk * B + bb2);
    }

    ull acc[4][4];                        // [m-frag(2m)][b]
    #pragma unroll
    for (int p = 0; p < 4; p++)
        #pragma unroll
        for (int j = 0; j < 4; j++) acc[p][j] = 0ull;

    for (int kt = 0; kt < 64; kt++) {
        const int buf = kt & 1;
        // stage current tile
        #pragma unroll
        for (int q = 0; q < 4; q++) {
            float4 v = ap[q];
            As[buf][4 * q + 0][lcol] = v.x;
            As[buf][4 * q + 1][lcol] = v.y;
            As[buf][4 * q + 2][lcol] = v.z;
            As[buf][4 * q + 3][lcol] = v.w;
        }
        *(float2*)&Bs[buf][bk][bb2] = bp;
        // prefetch next tile into regs (global only, no smem touch)
        if (kt + 1 < 64) {
            const int k0 = (kt + 1) * LKT;
            const float* wr = Wm + (size_t)tid * H + k0;
            #pragma unroll
            for (int q = 0; q < 4; q++) ap[q] = *(const float4*)(wr + 4 * q);
            bp = *(const float2*)(hb + (k0 + bk) * B + bb2);
        }
        __syncthreads();

        #pragma unroll
        for (int kk = 0; kk < LKT; kk++) {
            const float* ab = &As[buf][kk][160 * mh + 10 * tm];
            ull a0 = *(const ull*)(ab + 0);
            ull a1 = *(const ull*)(ab + 2);
            ull a2 = *(const ull*)(ab + 4);
            ull a3 = *(const ull*)(ab + 6);
            float4 bv = *(const float4*)&Bs[buf][kk][bbase + 4 * bq];
            ull s;
            s = splat2(bv.x); fma2(acc[0][0], a0, s); fma2(acc[1][0], a1, s); fma2(acc[2][0], a2, s); fma2(acc[3][0], a3, s);
            s = splat2(bv.y); fma2(acc[0][1], a0, s); fma2(acc[1][1], a1, s); fma2(acc[2][1], a2, s); fma2(acc[3][1], a3, s);
            s = splat2(bv.z); fma2(acc[0][2], a0, s); fma2(acc[1][2], a1, s); fma2(acc[2][2], a2, s); fma2(acc[3][2], a3, s);
            s = splat2(bv.w); fma2(acc[0][3], a0, s); fma2(acc[1][3], a1, s); fma2(acc[2][3], a2, s); fma2(acc[3][3], a3, s);
        }
        // no trailing sync: other buffer's last readers passed the sync above
    }

    // epilogue: bias, store, fused argmax
    const int mbase = m0 + 128 * mh + 8 * tm;
    float4 bias0 = *(const float4*)&bout[mbase];
    float4 bias1 = *(const float4*)&bout[mbase + 4];
    #pragma unroll
    for (int j = 0; j < 4; j++) {
        int b = bbase + 4 * bq + j;
        float2 q0 = unpk(acc[0][j]), q1 = unpk(acc[1][j]);
        float2 q2 = unpk(acc[2][j]), q3 = unpk(acc[3][j]);
        float4 o0 = make_float4(q0.x + bias0.x, q0.y + bias0.y, q1.x + bias0.z, q1.y + bias0.w);
        float4 o1 = make_float4(q2.x + bias1.x, q2.y + bias1.y, q3.x + bias1.z, q3.y + bias1.w);
        float* orow = out + ((size_t)b * T + t) * V + mbase;
        *(float4*)orow       = o0;
        *(float4*)(orow + 4) = o1;

        // thread-local argmax over 8 m (first-max tie rule: ascending m)
        float bv = o0.x; int bi = 0;
        if (o0.y > bv) { bv = o0.y; bi = 1; }
        if (o0.z > bv) { bv = o0.z; bi = 2; }
        if (o0.w > bv) { bv = o0.w; bi = 3; }
        if (o1.x > bv) { bv = o1.x; bi = 4; }
        if (o1.y > bv) { bv = o1.y; bi = 5; }
        if (o1.z > bv) { bv = o1.z; bi = 6; }
        if (o1.w > bv) { bv = o1.w; bi = 7; }
        int gidx = mbase + bi;
        // reduce across 16 tm-lanes (same b within each half-warp)
        #pragma unroll
        for (int off = 8; off > 0; off >>= 1) {
            float ov = __shfl_down_sync(0xffffffffu, bv, off, 16);
            int   oi = __shfl_down_sync(0xffffffffu, gidx, off, 16);
            if (ov > bv || (ov == bv && oi < gidx)) { bv = ov; gidx = oi; }
        }
        if (tm == 0) { sv[b][mh] = bv; si[b][mh] = gidx; }
    }
    __syncthreads();
    if (tid < B) {
        float v0 = sv[tid][0], v1 = sv[tid][1];
        int   i0 = si[tid][0], i1 = si[tid][1];
        bool take1 = (v1 > v0) || (v1 == v0 && i1 < i0);
        g_pval[tid][mt] = take1 ? v1 : v0;
        g_pidx[tid][mt] = take1 ? i1 : i0;
    }
}

// =====================================================================
// final argmax (for t = T-1 rowmax)
// =====================================================================
__global__ void __launch_bounds__(1024) argmax_last(int t)
{
    int b = threadIdx.x >> 5;
    int lane = threadIdx.x & 31;
    float v = -INFINITY;
    int idx = 0x7fffffff;
    for (int i = lane; i < NMT; i += 32) {
        float pv = g_pval[b][i];
        int   pi = g_pidx[b][i];
        if (pv > v || (pv == v && pi < idx)) { v = pv; idx = pi; }
    }
    #pragma unroll
    for (int off = 16; off > 0; off >>= 1) {
        float ov = __shfl_down_sync(0xffffffffu, v, off);
        int   oi = __shfl_down_sync(0xffffffffu, idx, off);
        if (ov > v || (ov == v && oi < idx)) { v = ov; idx = oi; }
    }
    if (lane == 0) {
        g_tok[b] = idx;
        g_rowmax[b * T + t] = v;
    }
}

// =====================================================================
// deferred log_softmax, in-place, one block per (b,t) row
// =====================================================================
__global__ void __launch_bounds__(256) lsm_k(float* __restrict__ out)
{
    __shared__ float red[256];
    int r = blockIdx.x;
    float4* row4 = (float4*)(out + (size_t)r * V);
    float mx = g_rowmax[r];
    float s = 0.f;
    for (int i = threadIdx.x; i < V / 4; i += 256) {
        float4 v = row4[i];
        s += expf(v.x - mx) + expf(v.y - mx) + expf(v.z - mx) + expf(v.w - mx);
    }
    red[threadIdx.x] = s;
    __syncthreads();
    for (int off = 128; off > 0; off >>= 1) {
        if (threadIdx.x < off) red[threadIdx.x] += red[threadIdx.x + off];
        __syncthreads();
    }
    float c = mx + logf(red[0]);
    for (int i = threadIdx.x; i < V / 4; i += 256) {
        float4 v = row4[i];
        v.x -= c; v.y -= c; v.z -= c; v.w -= c;
        row4[i] = v;
    }
}

// =====================================================================
// copy final hidden (buffer 0 after 64 steps) to output tail
// =====================================================================
__global__ void copy_h(float* __restrict__ dst)
{
    int b = blockIdx.x, k = threadIdx.x;
    dst[b * H + k] = g_h[0][k * B + b];
}

// =====================================================================
extern "C" void kernel_launch(void* const* d_in, const int* in_sizes, int n_in,
                              void* d_out, int out_size)
{
    const float* enc_h = (const float*)d_in[1];
    const float* emb   = (const float*)d_in[2];
    const float* Wih   = (const float*)d_in[3];
    const float* Whh   = (const float*)d_in[4];
    const float* bih   = (const float*)d_in[5];
    const float* bhh   = (const float*)d_in[6];
    const float* Wout  = (const float*)d_in[7];
    const float* bout  = (const float*)d_in[8];
    float* out = (float*)d_out;

    init_k<<<B, H>>>(enc_h);
    for (int t = 0; t < T; t++) {
        gru_gemm<<<dim3(48, KSP), 128>>>(Wih, Whh, emb, t);   // fused argmax(t-1)
        gru_cell<<<128, 256>>>(bih, bhh, t);
        logits_gemm<<<NMT, 256>>>(Wout, bout, out, t);
    }
    argmax_last<<<1, 1024>>>(T - 1);
    lsm_k<<<B * T, 256>>>(out);
    if ((long long)out_size >= OUT_LOGP + (long long)B * H)
        copy_h<<<B, H>>>(out + OUT_LOGP);
}

// round 10
// speedup vs baseline: 1.3306x; 1.3306x over previous
#include <cuda_runtime.h>
#include <math.h>
#include <stdint.h>

#define H    1024
#define V    32000
#define B    32
#define T    64
#define G3H  3072
#define BM   256               // logits m-tile
#define NMT  (V / BM)          // 125 logits m-tiles (single wave on 148 SMs)
#define KSP  4                 // GRU K-split
#define GPITCH 162             // gru As pitch (stride-10 groups, 16 tm lanes)
#define LPITCH 322             // logits As pitch: 322 mod 32 == 2
#define BPITCH 36
#define LKT  16                // logits k-tile (double buffered)
#define OUT_LOGP 65536000LL    // B*T*V

typedef unsigned long long ull;

// ---------------- device scratch (no allocations allowed) ----------------
__device__ float g_h[2][H * B];           // hidden, transposed [k][b], double buffer
__device__ float g_Cb[KSP][B][2 * G3H];   // GRU gate partials [ksplit][b][m]
__device__ float g_pval[B][NMT];          // per-m-tile argmax partials
__device__ int   g_pidx[B][NMT];
__device__ float g_rowmax[B * T];         // max logit per (b,t) for log_softmax
__device__ int   g_tok[B];

// ---------------- packed fp32x2 helpers ----------------
__device__ __forceinline__ ull splat2(float x) {
    ull r; asm("mov.b64 %0, {%1, %1};" : "=l"(r) : "f"(x)); return r;
}
__device__ __forceinline__ void fma2(ull& d, ull a, ull b) {
    asm("fma.rn.f32x2 %0, %1, %2, %0;" : "+l"(d) : "l"(a), "l"(b));
}
__device__ __forceinline__ float2 unpk(ull v) {
    float2 f; asm("mov.b64 {%0, %1}, %2;" : "=f"(f.x), "=f"(f.y) : "l"(v)); return f;
}

// map m-row r to stride-10 group column
__device__ __forceinline__ int acol(int r) { return (r >> 3) * 10 + (r & 7); }

// =====================================================================
// init: h0 = encoder_hidden[0] transposed; tok = SOS(0)
// =====================================================================
__global__ void init_k(const float* __restrict__ enc_h)
{
    int b = blockIdx.x, k = threadIdx.x;          // 32 x 1024
    g_h[0][k * B + b] = enc_h[b * H + k];
    if (b == 0 && k < B) g_tok[k] = 0;
}

// =====================================================================
// GRU gates GEMM, K-split (structure unchanged from R8).
// =====================================================================
__global__ void __launch_bounds__(128) gru_gemm(
    const float* __restrict__ Wih, const float* __restrict__ Whh,
    const float* __restrict__ emb, int t)
{
    const int m0 = blockIdx.x * 128;
    const int ks = blockIdx.y;
    const bool ih = (m0 < G3H);
    const float* __restrict__ Wm = ih ? (Wih + (size_t)m0 * H)
                                      : (Whh + (size_t)(m0 - G3H) * H);
    const float* __restrict__ hb = g_h[t & 1];

    __shared__ float As[32][GPITCH];
    __shared__ float Bs[32][BPITCH];
    __shared__ int   srow[B];

    const int tid = threadIdx.x;
    const int tm = tid & 15;
    const int tb = tid >> 4;
    const int lr = tid >> 2;
    const int lc = tid & 3;
    const int bk = tid >> 2;
    const int bb = (tid & 3) * 8;

    if (ih) {
        if (t > 0) {
            int b = tid >> 2, li = tid & 3;
            float v = -INFINITY; int idx = 0x7fffffff;
            for (int i = li; i < NMT; i += 4) {
                float pv = g_pval[b][i]; int pi = g_pidx[b][i];
                if (pv > v || (pv == v && pi < idx)) { v = pv; idx = pi; }
            }
            #pragma unroll
            for (int off = 2; off > 0; off >>= 1) {
                float ov = __shfl_down_sync(0xffffffffu, v, off, 4);
                int   oi = __shfl_down_sync(0xffffffffu, idx, off, 4);
                if (ov > v || (ov == v && oi < idx)) { v = ov; idx = oi; }
            }
            if (li == 0) {
                srow[b] = idx * H;
                if (blockIdx.x == 0 && ks == 0) g_rowmax[b * T + (t - 1)] = v;
            }
        } else if (tid < B) {
            srow[tid] = 0;
        }
        __syncthreads();
    }

    const int kbase = ks * (H / KSP);

    float4 apre[8];
    float4 bq0, bq1;
    {
        const int k0 = kbase;
        #pragma unroll
        for (int p = 0; p < 4; p++) {
            const float* wr = Wm + (size_t)(p * 32 + lr) * H + k0;
            apre[p * 2 + 0] = *(const float4*)(wr + 4 * lc);
            apre[p * 2 + 1] = *(const float4*)(wr + 16 + 4 * lc);
        }
        if (ih) {
            int kg = k0 + bk;
            bq0.x = fmaxf(emb[(size_t)srow[bb + 0] + kg], 0.f);
            bq0.y = fmaxf(emb[(size_t)srow[bb + 1] + kg], 0.f);
            bq0.z = fmaxf(emb[(size_t)srow[bb + 2] + kg], 0.f);
            bq0.w = fmaxf(emb[(size_t)srow[bb + 3] + kg], 0.f);
            bq1.x = fmaxf(emb[(size_t)srow[bb + 4] + kg], 0.f);
            bq1.y = fmaxf(emb[(size_t)srow[bb + 5] + kg], 0.f);
            bq1.z = fmaxf(emb[(size_t)srow[bb + 6] + kg], 0.f);
            bq1.w = fmaxf(emb[(size_t)srow[bb + 7] + kg], 0.f);
        } else {
            bq0 = *(const float4*)(hb + (k0 + bk) * B + bb);
            bq1 = *(const float4*)(hb + (k0 + bk) * B + bb + 4);
        }
    }

    ull acc[4][4];
    #pragma unroll
    for (int p = 0; p < 4; p++)
        #pragma unroll
        for (int j = 0; j < 4; j++) acc[p][j] = 0ull;

    for (int kt = 0; kt < 8; kt++) {
        #pragma unroll
        for (int p = 0; p < 4; p++) {
            int col = acol(p * 32 + lr);
            float4 v0 = apre[p * 2 + 0];
            float4 v1 = apre[p * 2 + 1];
            int ka = 4 * lc, kb2 = 16 + 4 * lc;
            As[ka + 0][col] = v0.x; As[ka + 1][col] = v0.y;
            As[ka + 2][col] = v0.z; As[ka + 3][col] = v0.w;
            As[kb2 + 0][col] = v1.x; As[kb2 + 1][col] = v1.y;
            As[kb2 + 2][col] = v1.z; As[kb2 + 3][col] = v1.w;
        }
        *(float4*)&Bs[bk][bb]     = bq0;
        *(float4*)&Bs[bk][bb + 4] = bq1;
        __syncthreads();

        if (kt + 1 < 8) {
            const int k0 = kbase + (kt + 1) * 32;
            #pragma unroll
            for (int p = 0; p < 4; p++) {
                const float* wr = Wm + (size_t)(p * 32 + lr) * H + k0;
                apre[p * 2 + 0] = *(const float4*)(wr + 4 * lc);
                apre[p * 2 + 1] = *(const float4*)(wr + 16 + 4 * lc);
            }
            if (ih) {
                int kg = k0 + bk;
                bq0.x = fmaxf(emb[(size_t)srow[bb + 0] + kg], 0.f);
                bq0.y = fmaxf(emb[(size_t)srow[bb + 1] + kg], 0.f);
                bq0.z = fmaxf(emb[(size_t)srow[bb + 2] + kg], 0.f);
                bq0.w = fmaxf(emb[(size_t)srow[bb + 3] + kg], 0.f);
                bq1.x = fmaxf(emb[(size_t)srow[bb + 4] + kg], 0.f);
                bq1.y = fmaxf(emb[(size_t)srow[bb + 5] + kg], 0.f);
                bq1.z = fmaxf(emb[(size_t)srow[bb + 6] + kg], 0.f);
                bq1.w = fmaxf(emb[(size_t)srow[bb + 7] + kg], 0.f);
            } else {
                bq0 = *(const float4*)(hb + (k0 + bk) * B + bb);
                bq1 = *(const float4*)(hb + (k0 + bk) * B + bb + 4);
            }
        }

        #pragma unroll 16
        for (int kk = 0; kk < 32; kk++) {
            const float* ab = &As[kk][10 * tm];
            ull a0 = *(const ull*)(ab + 0);
            ull a1 = *(const ull*)(ab + 2);
            ull a2 = *(const ull*)(ab + 4);
            ull a3 = *(const ull*)(ab + 6);
            float4 bv = *(const float4*)&Bs[kk][4 * tb];
            ull s;
            s = splat2(bv.x); fma2(acc[0][0], a0, s); fma2(acc[1][0], a1, s); fma2(acc[2][0], a2, s); fma2(acc[3][0], a3, s);
            s = splat2(bv.y); fma2(acc[0][1], a0, s); fma2(acc[1][1], a1, s); fma2(acc[2][1], a2, s); fma2(acc[3][1], a3, s);
            s = splat2(bv.z); fma2(acc[0][2], a0, s); fma2(acc[1][2], a1, s); fma2(acc[2][2], a2, s); fma2(acc[3][2], a3, s);
            s = splat2(bv.w); fma2(acc[0][3], a0, s); fma2(acc[1][3], a1, s); fma2(acc[2][3], a2, s); fma2(acc[3][3], a3, s);
        }
        __syncthreads();
    }

    #pragma unroll
    for (int j = 0; j < 4; j++) {
        int b = 4 * tb + j;
        float2 p0 = unpk(acc[0][j]), p1 = unpk(acc[1][j]);
        float2 p2 = unpk(acc[2][j]), p3 = unpk(acc[3][j]);
        float4 o0 = make_float4(p0.x, p0.y, p1.x, p1.y);
        float4 o1 = make_float4(p2.x, p2.y, p3.x, p3.y);
        *(float4*)&g_Cb[ks][b][m0 + 8 * tm]     = o0;
        *(float4*)&g_Cb[ks][b][m0 + 8 * tm + 4] = o1;
    }
}

// =====================================================================
// GRU cell: sum K-split partials + biases -> h_new (buffer (t+1)&1)
// =====================================================================
__global__ void __launch_bounds__(256) gru_cell(
    const float* __restrict__ bih, const float* __restrict__ bhh, int t)
{
    int gid = blockIdx.x * 256 + threadIdx.x;      // 32768
    int b = gid >> 10;
    int j = gid & 1023;
    float gir = 0.f, giz = 0.f, gin = 0.f, ghr = 0.f, ghz = 0.f, ghn = 0.f;
    #pragma unroll
    for (int s = 0; s < KSP; s++) {
        const float* C = g_Cb[s][b];
        gir += C[j];           giz += C[H + j];       gin += C[2 * H + j];
        ghr += C[G3H + j];     ghz += C[G3H + H + j]; ghn += C[G3H + 2 * H + j];
    }
    float r = 1.f / (1.f + expf(-(gir + bih[j]       + ghr + bhh[j])));
    float z = 1.f / (1.f + expf(-(giz + bih[H + j]   + ghz + bhh[H + j])));
    float n = tanhf(gin + bih[2 * H + j] + r * (ghn + bhh[2 * H + j]));
    float hold = g_h[t & 1][j * B + b];
    g_h[(t + 1) & 1][j * B + b] = (1.f - z) * n + z * hold;
}

// =====================================================================
// Logits GEMM: BM=256, grid=125 (one wave), 256 threads (2 warps/SMSP).
// Compute: 8 warps = 2 m-halves x 4 b-octets; lane tm=lane&15 (A LDS
// broadcast across half-warps), bq=lane>>4. Per-thread 8m x 4b.
// A loader: COALESCED — 4 threads per row (lr=tid>>2, lc=tid&3),
// 4 row-passes; 8 lines per LDG instead of 32 (R9's regression cause).
// Double-buffered smem, k-tile 16, one __syncthreads per tile.
// =====================================================================
__global__ void __launch_bounds__(256) logits_gemm(
    const float* __restrict__ Wout, const float* __restrict__ bout,
    float* __restrict__ out, int t)
{
    const int mt = blockIdx.x;
    const int m0 = mt * BM;
    const float* __restrict__ Wm = Wout + (size_t)m0 * H;
    const float* __restrict__ hb = g_h[(t + 1) & 1];

    __shared__ float As[2][LKT][LPITCH];  // [buf][kk][col], col=(m>>3)*10+(m&7)
    __shared__ float Bs[2][LKT][BPITCH];
    __shared__ float sv[B][2];            // per-b per-mhalf argmax partials
    __shared__ int   si[B][2];

    const int tid  = threadIdx.x;
    const int lane = tid & 31;
    const int w    = tid >> 5;
    const int mh   = w >> 2;              // m half: 0 -> m 0..127, 1 -> 128..255
    const int bbase = (w & 3) * 8;        // warp's 8-b octet
    const int tm   = lane & 15;
    const int bq   = lane >> 4;           // b quad within octet
    // A loader: 4 threads per row, 4 passes of 64 rows
    const int lr = tid >> 2;              // row 0..63 (+64*pass)
    const int lc = tid & 3;               // k quad (16 k per tile)
    // B loader
    const int bk  = tid >> 4;             // k 0..15
    const int bb2 = (tid & 15) * 2;       // b pair

    float4 ap[4];
    float2 bp;
    {
        #pragma unroll
        for (int p = 0; p < 4; p++)
            ap[p] = *(const float4*)(Wm + (size_t)(p * 64 + lr) * H + 4 * lc);
        bp = *(const float2*)(hb + bk * B + bb2);
    }

    ull acc[4][4];                        // [m-frag(2m)][b]
    #pragma unroll
    for (int p = 0; p < 4; p++)
        #pragma unroll
        for (int j = 0; j < 4; j++) acc[p][j] = 0ull;

    for (int kt = 0; kt < 64; kt++) {
        const int buf = kt & 1;
        // stage current tile (STS conflict-free: bank=8lc+lr+2i+16p mod 32)
        #pragma unroll
        for (int p = 0; p < 4; p++) {
            int col = acol(p * 64 + lr);
            float4 v = ap[p];
            int ka = 4 * lc;
            As[buf][ka + 0][col] = v.x;
            As[buf][ka + 1][col] = v.y;
            As[buf][ka + 2][col] = v.z;
            As[buf][ka + 3][col] = v.w;
        }
        *(float2*)&Bs[buf][bk][bb2] = bp;
        // prefetch next tile into regs (global only)
        if (kt + 1 < 64) {
            const int k0 = (kt + 1) * LKT;
            #pragma unroll
            for (int p = 0; p < 4; p++)
                ap[p] = *(const float4*)(Wm + (size_t)(p * 64 + lr) * H + k0 + 4 * lc);
            bp = *(const float2*)(hb + (k0 + bk) * B + bb2);
        }
        __syncthreads();

        #pragma unroll
        for (int kk = 0; kk < LKT; kk++) {
            const float* ab = &As[buf][kk][160 * mh + 10 * tm];
            ull a0 = *(const ull*)(ab + 0);
            ull a1 = *(const ull*)(ab + 2);
            ull a2 = *(const ull*)(ab + 4);
            ull a3 = *(const ull*)(ab + 6);
            float4 bv = *(const float4*)&Bs[buf][kk][bbase + 4 * bq];
            ull s;
            s = splat2(bv.x); fma2(acc[0][0], a0, s); fma2(acc[1][0], a1, s); fma2(acc[2][0], a2, s); fma2(acc[3][0], a3, s);
            s = splat2(bv.y); fma2(acc[0][1], a0, s); fma2(acc[1][1], a1, s); fma2(acc[2][1], a2, s); fma2(acc[3][1], a3, s);
            s = splat2(bv.z); fma2(acc[0][2], a0, s); fma2(acc[1][2], a1, s); fma2(acc[2][2], a2, s); fma2(acc[3][2], a3, s);
            s = splat2(bv.w); fma2(acc[0][3], a0, s); fma2(acc[1][3], a1, s); fma2(acc[2][3], a2, s); fma2(acc[3][3], a3, s);
        }
        // no trailing sync: next iteration's sync protects the other buffer
    }

    // epilogue: bias, store, fused argmax
    const int mbase = m0 + 128 * mh + 8 * tm;
    float4 bias0 = *(const float4*)&bout[mbase];
    float4 bias1 = *(const float4*)&bout[mbase + 4];
    #pragma unroll
    for (int j = 0; j < 4; j++) {
        int b = bbase + 4 * bq + j;
        float2 q0 = unpk(acc[0][j]), q1 = unpk(acc[1][j]);
        float2 q2 = unpk(acc[2][j]), q3 = unpk(acc[3][j]);
        float4 o0 = make_float4(q0.x + bias0.x, q0.y + bias0.y, q1.x + bias0.z, q1.y + bias0.w);
        float4 o1 = make_float4(q2.x + bias1.x, q2.y + bias1.y, q3.x + bias1.z, q3.y + bias1.w);
        float* orow = out + ((size_t)b * T + t) * V + mbase;
        *(float4*)orow       = o0;
        *(float4*)(orow + 4) = o1;

        // thread-local argmax over 8 m (first-max tie rule: ascending m)
        float bv = o0.x; int bi = 0;
        if (o0.y > bv) { bv = o0.y; bi = 1; }
        if (o0.z > bv) { bv = o0.z; bi = 2; }
        if (o0.w > bv) { bv = o0.w; bi = 3; }
        if (o1.x > bv) { bv = o1.x; bi = 4; }
        if (o1.y > bv) { bv = o1.y; bi = 5; }
        if (o1.z > bv) { bv = o1.z; bi = 6; }
        if (o1.w > bv) { bv = o1.w; bi = 7; }
        int gidx = mbase + bi;
        // reduce across 16 tm-lanes (same b within each half-warp)
        #pragma unroll
        for (int off = 8; off > 0; off >>= 1) {
            float ov = __shfl_down_sync(0xffffffffu, bv, off, 16);
            int   oi = __shfl_down_sync(0xffffffffu, gidx, off, 16);
            if (ov > bv || (ov == bv && oi < gidx)) { bv = ov; gidx = oi; }
        }
        if (tm == 0) { sv[b][mh] = bv; si[b][mh] = gidx; }
    }
    __syncthreads();
    if (tid < B) {
        float v0 = sv[tid][0], v1 = sv[tid][1];
        int   i0 = si[tid][0], i1 = si[tid][1];
        bool take1 = (v1 > v0) || (v1 == v0 && i1 < i0);
        g_pval[tid][mt] = take1 ? v1 : v0;
        g_pidx[tid][mt] = take1 ? i1 : i0;
    }
}

// =====================================================================
// final argmax (for t = T-1 rowmax)
// =====================================================================
__global__ void __launch_bounds__(1024) argmax_last(int t)
{
    int b = threadIdx.x >> 5;
    int lane = threadIdx.x & 31;
    float v = -INFINITY;
    int idx = 0x7fffffff;
    for (int i = lane; i < NMT; i += 32) {
        float pv = g_pval[b][i];
        int   pi = g_pidx[b][i];
        if (pv > v || (pv == v && pi < idx)) { v = pv; idx = pi; }
    }
    #pragma unroll
    for (int off = 16; off > 0; off >>= 1) {
        float ov = __shfl_down_sync(0xffffffffu, v, off);
        int   oi = __shfl_down_sync(0xffffffffu, idx, off);
        if (ov > v || (ov == v && oi < idx)) { v = ov; idx = oi; }
    }
    if (lane == 0) {
        g_tok[b] = idx;
        g_rowmax[b * T + t] = v;
    }
}

// =====================================================================
// deferred log_softmax, in-place, one block per (b,t) row
// =====================================================================
__global__ void __launch_bounds__(256) lsm_k(float* __restrict__ out)
{
    __shared__ float red[256];
    int r = blockIdx.x;
    float4* row4 = (float4*)(out + (size_t)r * V);
    float mx = g_rowmax[r];
    float s = 0.f;
    for (int i = threadIdx.x; i < V / 4; i += 256) {
        float4 v = row4[i];
        s += expf(v.x - mx) + expf(v.y - mx) + expf(v.z - mx) + expf(v.w - mx);
    }
    red[threadIdx.x] = s;
    __syncthreads();
    for (int off = 128; off > 0; off >>= 1) {
        if (threadIdx.x < off) red[threadIdx.x] += red[threadIdx.x + off];
        __syncthreads();
    }
    float c = mx + logf(red[0]);
    for (int i = threadIdx.x; i < V / 4; i += 256) {
        float4 v = row4[i];
        v.x -= c; v.y -= c; v.z -= c; v.w -= c;
        row4[i] = v;
    }
}

// =====================================================================
// copy final hidden (buffer 0 after 64 steps) to output tail
// =====================================================================
__global__ void copy_h(float* __restrict__ dst)
{
    int b = blockIdx.x, k = threadIdx.x;
    dst[b * H + k] = g_h[0][k * B + b];
}

// =====================================================================
extern "C" void kernel_launch(void* const* d_in, const int* in_sizes, int n_in,
                              void* d_out, int out_size)
{
    const float* enc_h = (const float*)d_in[1];
    const float* emb   = (const float*)d_in[2];
    const float* Wih   = (const float*)d_in[3];
    const float* Whh   = (const float*)d_in[4];
    const float* bih   = (const float*)d_in[5];
    const float* bhh   = (const float*)d_in[6];
    const float* Wout  = (const float*)d_in[7];
    const float* bout  = (const float*)d_in[8];
    float* out = (float*)d_out;

    init_k<<<B, H>>>(enc_h);
    for (int t = 0; t < T; t++) {
        gru_gemm<<<dim3(48, KSP), 128>>>(Wih, Whh, emb, t);   // fused argmax(t-1)
        gru_cell<<<128, 256>>>(bih, bhh, t);
        logits_gemm<<<NMT, 256>>>(Wout, bout, out, t);
    }
    argmax_last<<<1, 1024>>>(T - 1);
    lsm_k<<<B * T, 256>>>(out);
    if ((long long)out_size >= OUT_LOGP + (long long)B * H)
        copy_h<<<B, H>>>(out + OUT_LOGP);
}